// round 17
// baseline (speedup 1.0000x reference)
#include <cuda_runtime.h>
#include <cuda_bf16.h>
#include <cuda_fp16.h>
#include <cstdint>

// Problem constants
#define BB 32
#define SS 512
#define EE 300
#define EP 304          // padded K
#define EPH 152         // EP/2 (packed half2 words per row)
#define HH 128
#define G4 512          // 4*H
#define NN 1024         // fused fwd+bwd gate width

// Scratch (device globals; allocation-free rule)
__device__ __align__(16) __half g_X[(size_t)BB * SS * EP];  // fp16 embeddings [16384][304]
__device__ uint32_t g_Wp[(size_t)EPH * NN];   // packed half2 weights
__device__ float g_bias[NN];
__device__ float g_G[(size_t)BB * SS * NN];   // gate preactivations [16384][1024]
__device__ float g_pooled[BB * 2 * HH];       // [b][dir*128+idx]

// ---------- helpers ----------
__device__ __forceinline__ float tanh_ap(float x) {
    float y;
    asm("tanh.approx.f32 %0, %1;" : "=f"(y) : "f"(x));
    return y;
}
__device__ __forceinline__ void mma_f16(float* c,
                                        uint32_t a0, uint32_t a1, uint32_t a2, uint32_t a3,
                                        uint32_t b0, uint32_t b1) {
    asm volatile(
        "mma.sync.aligned.m16n8k16.row.col.f32.f16.f16.f32 "
        "{%0,%1,%2,%3}, {%4,%5,%6,%7}, {%8,%9}, {%0,%1,%2,%3};"
        : "+f"(c[0]), "+f"(c[1]), "+f"(c[2]), "+f"(c[3])
        : "r"(a0), "r"(a1), "r"(a2), "r"(a3), "r"(b0), "r"(b1));
}
__device__ __forceinline__ uint32_t pack_h2(float x, float y) {
    __half2 h2 = __floats2half2_rn(x, y);
    return *(uint32_t*)&h2;
}

// ---------- Kernel 1: pack input-projection weights (half2 pairs) + bias ----------
// Column permutation: packed col n = dir*512 + hu*4 + gi.
__global__ void pack_w_kernel(const float* __restrict__ Wih_f,
                              const float* __restrict__ Wih_b,
                              const float* __restrict__ b_f,
                              const float* __restrict__ b_b) {
    int idx = blockIdx.x * 256 + threadIdx.x;
    if (idx < EPH * NN) {
        int k2 = idx >> 10;                // 0..151
        int n = idx & 1023;
        int d = n >> 9, r = n & 511;
        int hu = r >> 2, gi = r & 3;
        int srow = gi * HH + hu;           // source gate row in Wih layout
        const float* Wsrc = d ? Wih_b : Wih_f;
        int k0 = 2 * k2, k1 = k0 + 1;
        float v0 = (k0 < EE) ? Wsrc[srow * EE + k0] : 0.0f;
        float v1 = (k1 < EE) ? Wsrc[srow * EE + k1] : 0.0f;
        g_Wp[idx] = pack_h2(v0, v1);
    }
    if (idx < NN) {
        int d = idx >> 9, r = idx & 511;
        int hu = r >> 2, gi = r & 3;
        int srow = gi * HH + hu;
        g_bias[idx] = d ? b_b[srow] : b_f[srow];
    }
}

// ---------- Kernel 2: embeddings with dep-mean blend (fp16 output) ----------
__global__ void embed_kernel(const int* __restrict__ word_ids,
                             const int* __restrict__ deps_ids,
                             const float* __restrict__ word_table,
                             const float* __restrict__ dep_table) {
    int bs = blockIdx.x;           // 0..16383
    int b = bs >> 9;
    int s = bs & 511;
    int wid = word_ids[b * (3 * SS) + SS + s];

    int ids[8];
    float cnt = 0.0f;
#pragma unroll
    for (int d = 0; d < 8; d++) {
        ids[d] = deps_ids[bs * 8 + d];
        if (ids[d] > 1) cnt += 1.0f;   // PAD=0, UNK=1
    }
    float inv = (cnt > 0.0f) ? 0.5f / cnt : 0.0f;
    float wscale = (cnt > 0.0f) ? 0.5f : 1.0f;

    for (int e = threadIdx.x; e < EP; e += 128) {
        float v = 0.0f;
        if (e < EE) {
            float w = word_table[(size_t)wid * EE + e];
            float sum = 0.0f;
#pragma unroll
            for (int d = 0; d < 8; d++) {
                if (ids[d] > 1) sum += dep_table[ids[d] * EE + e];
            }
            v = wscale * w + inv * sum;
        }
        g_X[(size_t)bs * EP + e] = __float2half(v);
    }
}

// ---------- Kernel 3: fp16 tensor-core GEMM G = X @ W + bias ----------
__global__ void __launch_bounds__(256, 2) gemm_tc_kernel() {
    __shared__ uint32_t As[128][12];   // [m][k2] (8 words + pad 4)
    __shared__ uint32_t Bs[8][132];    // [k2][n] (128 + pad 4)

    int tid = threadIdx.x;
    int bm = blockIdx.x * 128;
    int bn = blockIdx.y * 128;
    int lane = tid & 31, wid = tid >> 5;
    int wm = wid & 3, wn = wid >> 2;
    int g = lane >> 2, tg = lane & 3;

    float acc[2][8][4];
#pragma unroll
    for (int i = 0; i < 2; i++)
#pragma unroll
        for (int j = 0; j < 8; j++)
#pragma unroll
            for (int q = 0; q < 4; q++) acc[i][j][q] = 0.0f;

    int arow = tid >> 1, akq = (tid & 1) * 4;
    int bkr = tid >> 5, bnc = (tid & 31) * 4;
    const uint32_t* X32 = (const uint32_t*)g_X;

    uint4 aR = *(const uint4*)(X32 + (size_t)(bm + arow) * EPH + akq);
    uint4 bR = *(const uint4*)(g_Wp + (size_t)bkr * NN + bn + bnc);

    for (int kh = 0; kh < EPH; kh += 8) {
        __syncthreads();
        *(uint4*)&As[arow][akq] = aR;
        *(uint4*)&Bs[bkr][bnc] = bR;
        __syncthreads();

        if (kh + 8 < EPH) {
            aR = *(const uint4*)(X32 + (size_t)(bm + arow) * EPH + kh + 8 + akq);
            bR = *(const uint4*)(g_Wp + (size_t)(kh + 8 + bkr) * NN + bn + bnc);
        }

        uint32_t af[2][4];
#pragma unroll
        for (int i = 0; i < 2; i++) {
            int mr = wm * 32 + i * 16 + g;
            af[i][0] = As[mr][tg];
            af[i][1] = As[mr + 8][tg];
            af[i][2] = As[mr][tg + 4];
            af[i][3] = As[mr + 8][tg + 4];
        }
#pragma unroll
        for (int j = 0; j < 8; j++) {
            int nc = wn * 64 + j * 8 + g;
            uint32_t b0 = Bs[tg][nc];
            uint32_t b1 = Bs[tg + 4][nc];
#pragma unroll
            for (int i = 0; i < 2; i++)
                mma_f16(acc[i][j], af[i][0], af[i][1], af[i][2], af[i][3], b0, b1);
        }
    }

#pragma unroll
    for (int j = 0; j < 8; j++) {
        int col = bn + wn * 64 + j * 8 + tg * 2;
        float bc0 = g_bias[col], bc1 = g_bias[col + 1];
#pragma unroll
        for (int i = 0; i < 2; i++) {
            int row = bm + wm * 32 + i * 16 + g;
            *(float2*)(g_G + (size_t)row * NN + col) =
                make_float2(acc[i][j][0] + bc0, acc[i][j][1] + bc1);
            *(float2*)(g_G + (size_t)(row + 8) * NN + col) =
                make_float2(acc[i][j][2] + bc0, acc[i][j][3] + bc1);
        }
    }
}

// ---------- Kernel 4: LSTM scan — single CTA per chain, tensor-core dots ----------
// Whh (permuted rows r=hu*4+gi) lives in registers as fp16 mma A-fragments
// (64 regs/thread). Per step: every warp runs 16 m16n8k16 mmas with B = h
// broadcast into all 8 columns (so every column holds the true gate sums);
// lanes tg==0 store their 4 row-results to smem; bar.sync; threads 0..127
// (one per hidden unit) read their 4 contiguous gate sums + prefetched gpre
// float4, activate scalar (no shfl), store h as fp16; bar.sync.
// No cluster / DSMEM / mbarrier anywhere.
__global__ void __launch_bounds__(512, 1)
lstm_scan_kernel(const float* __restrict__ Whh_f, const float* __restrict__ Whh_b) {
    __shared__ __half hbuf[HH];          // current h (fp16)
    __shared__ float gs[G4];             // recurrent gate sums

    int tid = threadIdx.x;
    int lane = tid & 31, w = tid >> 5;
    int g = lane >> 2, tg = lane & 3;
    int b = blockIdx.x;
    int dir = blockIdx.y;
    const float* Whh = dir ? Whh_b : Whh_f;

    // ---- load Whh as resident A fragments (rows permuted r = hu*4+gi) ----
    // warp w covers permuted rows [32w, 32w+32); mtile i rows [32w+16i, +16).
    uint32_t A[2][8][4];
#pragma unroll
    for (int i = 0; i < 2; i++) {
        int r0 = 32 * w + 16 * i + g;
        int r1 = r0 + 8;
        int s0 = (r0 & 3) * HH + (r0 >> 2);   // source Wih-layout row
        int s1 = (r1 & 3) * HH + (r1 >> 2);
#pragma unroll
        for (int kt = 0; kt < 8; kt++) {
            int k0 = 16 * kt + 2 * tg;
            float2 v;
            v = *(const float2*)(Whh + (size_t)s0 * HH + k0);
            A[i][kt][0] = pack_h2(v.x, v.y);
            v = *(const float2*)(Whh + (size_t)s1 * HH + k0);
            A[i][kt][1] = pack_h2(v.x, v.y);
            v = *(const float2*)(Whh + (size_t)s0 * HH + k0 + 8);
            A[i][kt][2] = pack_h2(v.x, v.y);
            v = *(const float2*)(Whh + (size_t)s1 * HH + k0 + 8);
            A[i][kt][3] = pack_h2(v.x, v.y);
        }
    }

    if (tid < HH) hbuf[tid] = __float2half(0.0f);
    __syncthreads();

    // gpre stream (act threads only): permuted G cols dir*512 + 4*tid .. +3
    long stepoff = dir ? -(long)NN : (long)NN;
    const float* gp = dir
        ? (g_G + ((size_t)(b * SS + SS - 1)) * NN + G4 + 4 * tid)
        : (g_G + ((size_t)(b * SS)) * NN + (dir ? G4 : 0) + 4 * tid);
    // (dir==0 path: offset 0)
    float4 gpre = make_float4(0.f, 0.f, 0.f, 0.f);
    if (tid < HH) gpre = *(const float4*)gp;
    gp += stepoff;

    float c = 0.0f, hmax = -1e30f;

    for (int t = 0; t < SS; t++) {
        // ---- B fragments: h broadcast to all 8 mma columns ----
        const uint32_t* h2b = (const uint32_t*)hbuf;
        uint32_t B0[8], B1[8];
#pragma unroll
        for (int kt = 0; kt < 8; kt++) {
            B0[kt] = h2b[kt * 8 + tg];       // k = 16kt + 2tg, +1
            B1[kt] = h2b[kt * 8 + 4 + tg];   // k = 16kt + 8 + 2tg, +1
        }

        // ---- 16 mmas: 2 mtiles x (2 k-chains of 4) for ILP ----
        float C[2][2][4];
#pragma unroll
        for (int i = 0; i < 2; i++)
#pragma unroll
            for (int q = 0; q < 2; q++)
#pragma unroll
                for (int z = 0; z < 4; z++) C[i][q][z] = 0.0f;
#pragma unroll
        for (int kt = 0; kt < 4; kt++) {
            mma_f16(C[0][0], A[0][kt][0], A[0][kt][1], A[0][kt][2], A[0][kt][3],
                    B0[kt], B1[kt]);
            mma_f16(C[1][0], A[1][kt][0], A[1][kt][1], A[1][kt][2], A[1][kt][3],
                    B0[kt], B1[kt]);
            mma_f16(C[0][1], A[0][kt + 4][0], A[0][kt + 4][1], A[0][kt + 4][2], A[0][kt + 4][3],
                    B0[kt + 4], B1[kt + 4]);
            mma_f16(C[1][1], A[1][kt + 4][0], A[1][kt + 4][1], A[1][kt + 4][2], A[1][kt + 4][3],
                    B0[kt + 4], B1[kt + 4]);
        }

        // ---- store gate sums (all columns equal; lanes tg==0 write) ----
        if (tg == 0) {
            gs[32 * w + g]      = C[0][0][0] + C[0][1][0];   // row 32w+g
            gs[32 * w + 8 + g]  = C[0][0][2] + C[0][1][2];   // row 32w+8+g
            gs[32 * w + 16 + g] = C[1][0][0] + C[1][1][0];   // row 32w+16+g
            gs[32 * w + 24 + g] = C[1][0][2] + C[1][1][2];   // row 32w+24+g
        }
        __syncthreads();

        // ---- activation: one thread per hidden unit, no shfl ----
        if (tid < HH) {
            float4 gn = make_float4(0.f, 0.f, 0.f, 0.f);
            if (t + 1 < SS) gn = *(const float4*)gp;
            gp += stepoff;

            float4 gv = *(const float4*)&gs[4 * tid];
            float si = gv.x + gpre.x;
            float sf = gv.y + gpre.y;
            float sg = gv.z + gpre.z;
            float so = gv.w + gpre.w;
            float ig = fmaf(0.5f, tanh_ap(0.5f * si), 0.5f);
            float fg = fmaf(0.5f, tanh_ap(0.5f * sf), 0.5f);
            float og = fmaf(0.5f, tanh_ap(0.5f * so), 0.5f);
            c = fg * c + ig * tanh_ap(sg);
            float hh = og * tanh_ap(c);
            hmax = fmaxf(hmax, hh);
            hbuf[tid] = __float2half(hh);
            gpre = gn;
        }
        __syncthreads();
    }

    if (tid < HH) g_pooled[b * 256 + dir * HH + tid] = hmax;
}

// ---------- Kernel 5: classifier ----------
__global__ void cls_kernel(const float* __restrict__ W_cls,
                           const float* __restrict__ b_cls,
                           float* __restrict__ out) {
    int t = threadIdx.x;
    if (t >= BB * 5) return;
    int b = t / 5, l = t % 5;
    float s = b_cls[l];
#pragma unroll 8
    for (int k = 0; k < 256; k++) s += g_pooled[b * 256 + k] * W_cls[l * 256 + k];
    out[b * 5 + l] = s;
}

// ---------- launch ----------
extern "C" void kernel_launch(void* const* d_in, const int* in_sizes, int n_in,
                              void* d_out, int out_size) {
    const int*   word_ids   = (const int*)d_in[0];
    const int*   deps_ids   = (const int*)d_in[1];
    const float* word_table = (const float*)d_in[2];
    const float* dep_table  = (const float*)d_in[3];
    const float* Wih_f      = (const float*)d_in[4];
    const float* Whh_f      = (const float*)d_in[5];
    const float* b_f        = (const float*)d_in[6];
    const float* Wih_b      = (const float*)d_in[7];
    const float* Whh_b      = (const float*)d_in[8];
    const float* b_b        = (const float*)d_in[9];
    const float* W_cls      = (const float*)d_in[10];
    const float* b_cls      = (const float*)d_in[11];
    float* out = (float*)d_out;

    pack_w_kernel<<<(EPH * NN + 255) / 256, 256>>>(Wih_f, Wih_b, b_f, b_b);
    embed_kernel<<<BB * SS, 128>>>(word_ids, deps_ids, word_table, dep_table);
    gemm_tc_kernel<<<dim3(128, 8), 256>>>();
    // one CTA per (batch, dir) chain — 64 CTAs, no cluster
    lstm_scan_kernel<<<dim3(BB, 2), 512>>>(Whh_f, Whh_b);
    cls_kernel<<<1, 256>>>(W_cls, b_cls, out);
}